// round 5
// baseline (speedup 1.0000x reference)
#include <cuda_runtime.h>
#include <cuda_bf16.h>
#include <cstddef>

// Problem constants
#define B_SZ    16
#define S_SZ    16
#define H_SZ    16
#define HD      64
#define D_MODEL 1024
#define PAST    4096
#define L_TOT   4112
#define M_ROWS  256
#define NSPLIT  8
#define TILE    32

// Output layout offsets (floats): y | k | v
#define OUT_Y_OFF 0
#define OUT_K_OFF (256*1024)
#define OUT_V_OFF (OUT_K_OFF + 256*4112*64)

// Scratch (device globals; no allocations allowed)
__device__ float g_qkv [M_ROWS * 3 * D_MODEL];     // [256, 3072]
__device__ float g_obuf[M_ROWS * D_MODEL];         // [256, 1024]
__device__ float g_po  [256 * NSPLIT * 16 * 64];
__device__ float g_pm  [256 * NSPLIT * 16];
__device__ float g_pl  [256 * NSPLIT * 16];

// ---------------------------------------------------------------------------
// GEMM: C[M,N] = A[M,K] @ W[N,K]^T + bias[N]   (row-major fp32)
// ---------------------------------------------------------------------------
__global__ __launch_bounds__(256)
void gemm_bias_kernel(const float* __restrict__ A, const float* __restrict__ W,
                      const float* __restrict__ bias, float* __restrict__ C,
                      int N, int K) {
    __shared__ float As[16][68];
    __shared__ float Bs[16][68];

    const int tid = threadIdx.x;
    const int tx = tid & 15;
    const int ty = tid >> 4;
    const int m0 = blockIdx.y * 64;
    const int n0 = blockIdx.x * 64;
    const int lr = tid >> 2;
    const int lk = (tid & 3) * 4;

    float c[4][4] = {};

    for (int k0 = 0; k0 < K; k0 += 16) {
        float4 a4 = *(const float4*)&A[(size_t)(m0 + lr) * K + k0 + lk];
        float4 b4 = *(const float4*)&W[(size_t)(n0 + lr) * K + k0 + lk];
        As[lk + 0][lr] = a4.x; As[lk + 1][lr] = a4.y;
        As[lk + 2][lr] = a4.z; As[lk + 3][lr] = a4.w;
        Bs[lk + 0][lr] = b4.x; Bs[lk + 1][lr] = b4.y;
        Bs[lk + 2][lr] = b4.z; Bs[lk + 3][lr] = b4.w;
        __syncthreads();

        #pragma unroll
        for (int kk = 0; kk < 16; kk++) {
            float4 av = *(const float4*)&As[kk][ty * 4];
            float4 bv = *(const float4*)&Bs[kk][tx * 4];
            c[0][0] += av.x * bv.x; c[0][1] += av.x * bv.y;
            c[0][2] += av.x * bv.z; c[0][3] += av.x * bv.w;
            c[1][0] += av.y * bv.x; c[1][1] += av.y * bv.y;
            c[1][2] += av.y * bv.z; c[1][3] += av.y * bv.w;
            c[2][0] += av.z * bv.x; c[2][1] += av.z * bv.y;
            c[2][2] += av.z * bv.z; c[2][3] += av.z * bv.w;
            c[3][0] += av.w * bv.x; c[3][1] += av.w * bv.y;
            c[3][2] += av.w * bv.z; c[3][3] += av.w * bv.w;
        }
        __syncthreads();
    }

    float4 bb = *(const float4*)&bias[n0 + tx * 4];
    #pragma unroll
    for (int i = 0; i < 4; i++) {
        float4 r = make_float4(c[i][0] + bb.x, c[i][1] + bb.y,
                               c[i][2] + bb.z, c[i][3] + bb.w);
        *(float4*)&C[(size_t)(m0 + ty * 4 + i) * N + n0 + tx * 4] = r;
    }
}

// ---------------------------------------------------------------------------
// Scatter freshly projected K/V rows into positions [4096, 4112).
// ---------------------------------------------------------------------------
__global__ __launch_bounds__(256)
void scatter_newkv_kernel(float* __restrict__ Kd, float* __restrict__ Vd) {
    const unsigned i = blockIdx.x * 256u + threadIdx.x;    // < 65536
    const unsigned c = i & 15u;
    const unsigned s = (i >> 4) & 15u;
    const unsigned h = (i >> 8) & 15u;
    const unsigned b = i >> 12;
    const size_t qoff = (size_t)(b * 16 + s) * 3072 + h * 64 + c * 4;
    const size_t doff = ((size_t)(b * 16 + h) * L_TOT + PAST + s) * 64 + c * 4;
    *(float4*)&Kd[doff] = *(const float4*)&g_qkv[qoff + 1024];
    *(float4*)&Vd[doff] = *(const float4*)&g_qkv[qoff + 2048];
}

// ---------------------------------------------------------------------------
// Fused attention + cache copy-out. Split-KV x8, 128 threads, 32-row tiles,
// register-prefetch software pipeline (LDG for tile t+1 issued while tile t
// computes; scoreboard wait absorbed at next STS).
// ---------------------------------------------------------------------------
__global__ __launch_bounds__(128)
void attn_split_kernel(const float* __restrict__ cache_k,
                       const float* __restrict__ cache_v,
                       float* __restrict__ out_k,
                       float* __restrict__ out_v) {
    __shared__ float qs [16][68];
    __shared__ float kt [TILE][68];
    __shared__ float vt [TILE][64];
    __shared__ float ptT[16][36];
    __shared__ float m_run[16], l_run[16], fac_s[16];

    const int tid   = threadIdx.x;
    const int bh    = blockIdx.x >> 3;
    const int split = blockIdx.x & 7;
    const int b = bh >> 4, h = bh & 15;

    // Load q (pre-scaled by 1/sqrt(64)): 16q x 16 float4 = 2 per thread
    #pragma unroll
    for (int i = 0; i < 2; i++) {
        const int idx = i * 128 + tid;
        const int q = idx >> 4, c4 = idx & 15;
        float4 qv = *(const float4*)&g_qkv[(size_t)(b * 16 + q) * 3072 + h * 64 + c4 * 4];
        qs[q][c4 * 4 + 0] = qv.x * 0.125f;
        qs[q][c4 * 4 + 1] = qv.y * 0.125f;
        qs[q][c4 * 4 + 2] = qv.z * 0.125f;
        qs[q][c4 * 4 + 3] = qv.w * 0.125f;
    }
    if (tid < 16) { m_run[tid] = -1e30f; l_run[tid] = 0.0f; }

    const int chunk0 = split * 512;
    const int nrows  = (split == 7) ? 528 : 512;
    const int ntiles = (split == 7) ? 17 : 16;
    const size_t cbase = (size_t)bh * (PAST * 64);
    const size_t obase = (size_t)bh * (L_TOT * 64);

    // phase mappings (128 threads)
    const int qg   = tid >> 5;          // score: query group 0..3 (fixed per warp)
    const int kp   = tid & 31;          // score: k row
    const int pq   = tid >> 3;          // softmax/AV: query 0..15
    const int dseg = tid & 7;           // softmax: 4-score segment / AV: 8-dim group

    // prefetch thread mapping
    const int lr = tid >> 4;            // base row 0..7 (i adds 8*i)
    const int lc = tid & 15;            // float4 column

    float4 oa = make_float4(0.f,0.f,0.f,0.f);   // dims dseg*8 .. +3
    float4 ob = make_float4(0.f,0.f,0.f,0.f);   // dims dseg*8+4 .. +7

    float4 pk[4], pv[4];

    // ---- prologue: prefetch tile 0 ----
    {
        const int l0 = chunk0;
        #pragma unroll
        for (int i = 0; i < 4; i++) {
            const int r = lr + i * 8;
            const int gl = l0 + r;
            const size_t off = (size_t)gl * 64 + lc * 4;
            if (gl < PAST) {
                pk[i] = *(const float4*)&cache_k[cbase + off];
                pv[i] = *(const float4*)&cache_v[cbase + off];
            } else {
                pk[i] = *(const float4*)&out_k[obase + off];
                pv[i] = *(const float4*)&out_v[obase + off];
            }
        }
    }

    for (int t = 0; t < ntiles; t++) {
        const int l0   = chunk0 + t * TILE;
        const int rows = min(TILE, chunk0 + nrows - l0);   // 32 or 16

        // ---- STS staged tile + copy-out to output KV ----
        #pragma unroll
        for (int i = 0; i < 4; i++) {
            const int r = lr + i * 8;
            if (r < rows) {
                const int gl = l0 + r;
                *(float4*)&kt[r][lc * 4] = pk[i];
                *(float4*)&vt[r][lc * 4] = pv[i];
                if (gl < PAST) {
                    const size_t off = (size_t)gl * 64 + lc * 4;
                    *(float4*)&out_k[obase + off] = pk[i];
                    *(float4*)&out_v[obase + off] = pv[i];
                }
            }
        }
        __syncthreads();

        // ---- prefetch tile t+1 (no wait until next STS) ----
        if (t + 1 < ntiles) {
            const int l1 = l0 + TILE;
            const int rows1 = min(TILE, chunk0 + nrows - l1);
            #pragma unroll
            for (int i = 0; i < 4; i++) {
                const int r = lr + i * 8;
                if (r < rows1) {
                    const int gl = l1 + r;
                    const size_t off = (size_t)gl * 64 + lc * 4;
                    if (gl < PAST) {
                        pk[i] = *(const float4*)&cache_k[cbase + off];
                        pv[i] = *(const float4*)&cache_v[cbase + off];
                    } else {
                        pk[i] = *(const float4*)&out_k[obase + off];
                        pv[i] = *(const float4*)&out_v[obase + off];
                    }
                }
            }
        }

        // ---- scores: thread = (4 queries qg*4.., k row kp) ----
        {
            float a0 = 0.f, a1 = 0.f, a2 = 0.f, a3 = 0.f;
            #pragma unroll
            for (int c = 0; c < 16; c++) {
                float4 k4 = *(const float4*)&kt[kp][c * 4];
                float4 q0 = *(const float4*)&qs[qg * 4 + 0][c * 4];
                float4 q1 = *(const float4*)&qs[qg * 4 + 1][c * 4];
                float4 q2 = *(const float4*)&qs[qg * 4 + 2][c * 4];
                float4 q3 = *(const float4*)&qs[qg * 4 + 3][c * 4];
                a0 += k4.x*q0.x + k4.y*q0.y + k4.z*q0.z + k4.w*q0.w;
                a1 += k4.x*q1.x + k4.y*q1.y + k4.z*q1.z + k4.w*q1.w;
                a2 += k4.x*q2.x + k4.y*q2.y + k4.z*q2.z + k4.w*q2.w;
                a3 += k4.x*q3.x + k4.y*q3.y + k4.z*q3.z + k4.w*q3.w;
            }
            const bool valid = kp < rows;
            ptT[qg * 4 + 0][kp] = valid ? a0 : -1e30f;
            ptT[qg * 4 + 1][kp] = valid ? a1 : -1e30f;
            ptT[qg * 4 + 2][kp] = valid ? a2 : -1e30f;
            ptT[qg * 4 + 3][kp] = valid ? a3 : -1e30f;
        }
        __syncthreads();

        // ---- softmax partial: thread = (q=pq, seg=dseg) over 4 scores ----
        {
            float4 p = *(const float4*)&ptT[pq][dseg * 4];
            float mt = fmaxf(fmaxf(p.x, p.y), fmaxf(p.z, p.w));
            #pragma unroll
            for (int s = 4; s >= 1; s >>= 1)
                mt = fmaxf(mt, __shfl_xor_sync(0xffffffffu, mt, s, 8));
            const float mo = m_run[pq];
            const float mn = fmaxf(mo, mt);
            const float fc = __expf(mo - mn);
            p.x = __expf(p.x - mn); p.y = __expf(p.y - mn);
            p.z = __expf(p.z - mn); p.w = __expf(p.w - mn);
            *(float4*)&ptT[pq][dseg * 4] = p;
            float ss = p.x + p.y + p.z + p.w;
            #pragma unroll
            for (int s = 4; s >= 1; s >>= 1)
                ss += __shfl_xor_sync(0xffffffffu, ss, s, 8);
            if (dseg == 0) {
                m_run[pq] = mn;
                fac_s[pq] = fc;
                l_run[pq] = l_run[pq] * fc + ss;
            }
        }
        __syncthreads();

        // ---- AV: thread = (pq, dseg): 8 dims over 32 rows ----
        {
            const float f = fac_s[pq];
            oa.x *= f; oa.y *= f; oa.z *= f; oa.w *= f;
            ob.x *= f; ob.y *= f; ob.z *= f; ob.w *= f;

            #pragma unroll
            for (int r0 = 0; r0 < TILE; r0 += 4) {
                float4 p4 = *(const float4*)&ptT[pq][r0];
                float4 va0 = *(const float4*)&vt[r0 + 0][dseg * 8];
                float4 vb0 = *(const float4*)&vt[r0 + 0][dseg * 8 + 4];
                float4 va1 = *(const float4*)&vt[r0 + 1][dseg * 8];
                float4 vb1 = *(const float4*)&vt[r0 + 1][dseg * 8 + 4];
                float4 va2 = *(const float4*)&vt[r0 + 2][dseg * 8];
                float4 vb2 = *(const float4*)&vt[r0 + 2][dseg * 8 + 4];
                float4 va3 = *(const float4*)&vt[r0 + 3][dseg * 8];
                float4 vb3 = *(const float4*)&vt[r0 + 3][dseg * 8 + 4];
                oa.x += p4.x*va0.x + p4.y*va1.x + p4.z*va2.x + p4.w*va3.x;
                oa.y += p4.x*va0.y + p4.y*va1.y + p4.z*va2.y + p4.w*va3.y;
                oa.z += p4.x*va0.z + p4.y*va1.z + p4.z*va2.z + p4.w*va3.z;
                oa.w += p4.x*va0.w + p4.y*va1.w + p4.z*va2.w + p4.w*va3.w;
                ob.x += p4.x*vb0.x + p4.y*vb1.x + p4.z*vb2.x + p4.w*vb3.x;
                ob.y += p4.x*vb0.y + p4.y*vb1.y + p4.z*vb2.y + p4.w*vb3.y;
                ob.z += p4.x*vb0.z + p4.y*vb1.z + p4.z*vb2.z + p4.w*vb3.z;
                ob.w += p4.x*vb0.w + p4.y*vb1.w + p4.z*vb2.w + p4.w*vb3.w;
            }
        }
        __syncthreads();   // tile fully consumed; safe to overwrite next iter
    }

    // ---- write partials ----
    {
        const size_t pbase = (size_t)blockIdx.x * 1024 + pq * 64 + dseg * 8;
        *(float4*)&g_po[pbase]     = oa;
        *(float4*)&g_po[pbase + 4] = ob;
    }
    if (tid < 16) {
        g_pm[blockIdx.x * 16 + tid] = m_run[tid];
        g_pl[blockIdx.x * 16 + tid] = l_run[tid];
    }
}

// ---------------------------------------------------------------------------
// Combine split partials -> g_obuf [B,S,H*hd]
// ---------------------------------------------------------------------------
__global__ __launch_bounds__(256)
void attn_reduce_kernel() {
    const int bh = blockIdx.x;
    const int tid = threadIdx.x;
    const int pq = tid >> 4, dc = tid & 15;
    const int base = bh * NSPLIT;

    float mm = -1e30f;
    #pragma unroll
    for (int s = 0; s < NSPLIT; s++)
        mm = fmaxf(mm, g_pm[(base + s) * 16 + pq]);

    float4 acc = make_float4(0.f, 0.f, 0.f, 0.f);
    float l = 0.f;
    #pragma unroll
    for (int s = 0; s < NSPLIT; s++) {
        float w = __expf(g_pm[(base + s) * 16 + pq] - mm);
        float4 o = *(const float4*)&g_po[(size_t)(base + s) * 1024 + pq * 64 + dc * 4];
        acc.x += w * o.x; acc.y += w * o.y;
        acc.z += w * o.z; acc.w += w * o.w;
        l += w * g_pl[(base + s) * 16 + pq];
    }
    float inv = 1.0f / l;
    const int b = bh >> 4, h = bh & 15;
    float4 r = make_float4(acc.x * inv, acc.y * inv, acc.z * inv, acc.w * inv);
    *(float4*)&g_obuf[(size_t)(b * 16 + pq) * D_MODEL + h * 64 + dc * 4] = r;
}

// ---------------------------------------------------------------------------
extern "C" void kernel_launch(void* const* d_in, const int* in_sizes, int n_in,
                              void* d_out, int out_size) {
    const float* x       = (const float*)d_in[0];
    const float* cache_k = (const float*)d_in[1];
    const float* cache_v = (const float*)d_in[2];
    const float* qkv_w   = (const float*)d_in[3];
    const float* qkv_b   = (const float*)d_in[4];
    const float* out_w   = (const float*)d_in[5];
    const float* out_b   = (const float*)d_in[6];

    float* out   = (float*)d_out;
    float* out_y = out + OUT_Y_OFF;
    float* out_k = out + OUT_K_OFF;
    float* out_v = out + OUT_V_OFF;

    float *qkv_p = nullptr, *obuf_p = nullptr;
    cudaGetSymbolAddress((void**)&qkv_p,  g_qkv);
    cudaGetSymbolAddress((void**)&obuf_p, g_obuf);

    // 1) QKV projection -> g_qkv [256,3072]
    gemm_bias_kernel<<<dim3(3072 / 64, M_ROWS / 64), 256>>>(
        x, qkv_w, qkv_b, qkv_p, 3072, D_MODEL);

    // 2) Append new K/V rows into out_k/out_v tails
    scatter_newkv_kernel<<<256, 256>>>(out_k, out_v);

    // 3) Fused attention + cache copy-out (split-KV x8, pipelined)
    attn_split_kernel<<<B_SZ * H_SZ * NSPLIT, 128>>>(cache_k, cache_v, out_k, out_v);

    // 4) Combine splits -> g_obuf
    attn_reduce_kernel<<<B_SZ * H_SZ, 256>>>();

    // 5) Output projection -> y
    gemm_bias_kernel<<<dim3(D_MODEL / 64, M_ROWS / 64), 256>>>(
        obuf_p, out_w, out_b, out_y, D_MODEL, D_MODEL);
}

// round 6
// speedup vs baseline: 1.2826x; 1.2826x over previous
#include <cuda_runtime.h>
#include <cuda_bf16.h>
#include <cstddef>

// Problem constants
#define B_SZ    16
#define S_SZ    16
#define H_SZ    16
#define HD      64
#define D_MODEL 1024
#define PAST    4096
#define L_TOT   4112
#define M_ROWS  256
#define NSPLIT  4
#define TILE    32

// Output layout offsets (floats): y | k | v
#define OUT_Y_OFF 0
#define OUT_K_OFF (256*1024)
#define OUT_V_OFF (OUT_K_OFF + 256*4112*64)

// cp.async helpers (16B, L2-only: no L1 reuse for streamed KV)
__device__ __forceinline__ unsigned smem_u32(const void* p) {
    return (unsigned)__cvta_generic_to_shared(p);
}
#define CP_ASYNC16(dst_u32, src_ptr) \
    asm volatile("cp.async.cg.shared.global [%0], [%1], 16;\n" \
                 :: "r"(dst_u32), "l"(src_ptr))
#define CP_COMMIT() asm volatile("cp.async.commit_group;\n" ::)
#define CP_WAIT1()  asm volatile("cp.async.wait_group 1;\n" ::)
#define CP_WAIT0()  asm volatile("cp.async.wait_group 0;\n" ::)

// Scratch (device globals; no allocations allowed)
__device__ float g_qkv [M_ROWS * 3 * D_MODEL];     // [256, 3072]
__device__ float g_obuf[M_ROWS * D_MODEL];         // [256, 1024]
__device__ float g_po  [256 * NSPLIT * 16 * 64];
__device__ float g_pm  [256 * NSPLIT * 16];
__device__ float g_pl  [256 * NSPLIT * 16];

// ---------------------------------------------------------------------------
// GEMM: C[M,N] = A[M,K] @ W[N,K]^T + bias[N]   (row-major fp32)
// ---------------------------------------------------------------------------
__global__ __launch_bounds__(256)
void gemm_bias_kernel(const float* __restrict__ A, const float* __restrict__ W,
                      const float* __restrict__ bias, float* __restrict__ C,
                      int N, int K) {
    __shared__ float As[16][68];
    __shared__ float Bs[16][68];

    const int tid = threadIdx.x;
    const int tx = tid & 15;
    const int ty = tid >> 4;
    const int m0 = blockIdx.y * 64;
    const int n0 = blockIdx.x * 64;
    const int lr = tid >> 2;
    const int lk = (tid & 3) * 4;

    float c[4][4] = {};

    for (int k0 = 0; k0 < K; k0 += 16) {
        float4 a4 = *(const float4*)&A[(size_t)(m0 + lr) * K + k0 + lk];
        float4 b4 = *(const float4*)&W[(size_t)(n0 + lr) * K + k0 + lk];
        As[lk + 0][lr] = a4.x; As[lk + 1][lr] = a4.y;
        As[lk + 2][lr] = a4.z; As[lk + 3][lr] = a4.w;
        Bs[lk + 0][lr] = b4.x; Bs[lk + 1][lr] = b4.y;
        Bs[lk + 2][lr] = b4.z; Bs[lk + 3][lr] = b4.w;
        __syncthreads();

        #pragma unroll
        for (int kk = 0; kk < 16; kk++) {
            float4 av = *(const float4*)&As[kk][ty * 4];
            float4 bv = *(const float4*)&Bs[kk][tx * 4];
            c[0][0] += av.x * bv.x; c[0][1] += av.x * bv.y;
            c[0][2] += av.x * bv.z; c[0][3] += av.x * bv.w;
            c[1][0] += av.y * bv.x; c[1][1] += av.y * bv.y;
            c[1][2] += av.y * bv.z; c[1][3] += av.y * bv.w;
            c[2][0] += av.z * bv.x; c[2][1] += av.z * bv.y;
            c[2][2] += av.z * bv.z; c[2][3] += av.z * bv.w;
            c[3][0] += av.w * bv.x; c[3][1] += av.w * bv.y;
            c[3][2] += av.w * bv.z; c[3][3] += av.w * bv.w;
        }
        __syncthreads();
    }

    float4 bb = *(const float4*)&bias[n0 + tx * 4];
    #pragma unroll
    for (int i = 0; i < 4; i++) {
        float4 r = make_float4(c[i][0] + bb.x, c[i][1] + bb.y,
                               c[i][2] + bb.z, c[i][3] + bb.w);
        *(float4*)&C[(size_t)(m0 + ty * 4 + i) * N + n0 + tx * 4] = r;
    }
}

// ---------------------------------------------------------------------------
// Scatter freshly projected K/V rows into positions [4096, 4112).
// ---------------------------------------------------------------------------
__global__ __launch_bounds__(256)
void scatter_newkv_kernel(float* __restrict__ Kd, float* __restrict__ Vd) {
    const unsigned i = blockIdx.x * 256u + threadIdx.x;    // < 65536
    const unsigned c = i & 15u;
    const unsigned s = (i >> 4) & 15u;
    const unsigned h = (i >> 8) & 15u;
    const unsigned b = i >> 12;
    const size_t qoff = (size_t)(b * 16 + s) * 3072 + h * 64 + c * 4;
    const size_t doff = ((size_t)(b * 16 + h) * L_TOT + PAST + s) * 64 + c * 4;
    *(float4*)&Kd[doff] = *(const float4*)&g_qkv[qoff + 1024];
    *(float4*)&Vd[doff] = *(const float4*)&g_qkv[qoff + 2048];
}

// ---------------------------------------------------------------------------
// Fused attention + cache copy-out. Split-KV x4, 256 threads, 32-row tiles,
// cp.async DOUBLE-BUFFERED staging: tile t+1 streams into the alternate
// smem buffer while tile t computes. Copy-out to out_k/out_v is re-sourced
// from smem during the compute phase.
// ---------------------------------------------------------------------------
__global__ __launch_bounds__(256)
void attn_split_kernel(const float* __restrict__ cache_k,
                       const float* __restrict__ cache_v,
                       float* __restrict__ out_k,
                       float* __restrict__ out_v) {
    __shared__ float qs [16][68];
    __shared__ float kt [2][TILE][68];
    __shared__ float vt [2][TILE][64];
    __shared__ float ptT[16][36];
    __shared__ float m_run[16], l_run[16], fac_s[16];

    const int tid   = threadIdx.x;
    const int bh    = blockIdx.x >> 2;
    const int split = blockIdx.x & 3;
    const int b = bh >> 4, h = bh & 15;

    // Load q (pre-scaled by 1/sqrt(64)): one float4 per thread
    {
        const int q = tid >> 4, c4 = tid & 15;
        float4 qv = *(const float4*)&g_qkv[(size_t)(b * 16 + q) * 3072 + h * 64 + c4 * 4];
        qs[q][c4 * 4 + 0] = qv.x * 0.125f;
        qs[q][c4 * 4 + 1] = qv.y * 0.125f;
        qs[q][c4 * 4 + 2] = qv.z * 0.125f;
        qs[q][c4 * 4 + 3] = qv.w * 0.125f;
    }
    if (tid < 16) { m_run[tid] = -1e30f; l_run[tid] = 0.0f; }

    const int chunk0 = split * 1024;
    const int nrows  = (split == 3) ? 1040 : 1024;
    const int ntiles = (split == 3) ? 33 : 32;
    const size_t cbase = (size_t)bh * (PAST * 64);
    const size_t obase = (size_t)bh * (L_TOT * 64);

    // staging/copy-out mapping: 2 float4 slots per thread per tensor
    const int sr = tid >> 4;           // rows sr, sr+16
    const int sc = tid & 15;           // float4 column

    // score mapping: thread = (2 queries qg*2.., k row kp)
    const int qg = tid >> 5;           // 0..7
    const int kp = tid & 31;

    // softmax/AV mapping
    const int pq = tid >> 4;           // query 0..15
    const int dc = tid & 15;           // softmax: 2-score segment / AV: 4-dim chunk

    float4 oacc = make_float4(0.f, 0.f, 0.f, 0.f);

    // ---- stage one 32-row tile via cp.async into buffer bb ----
    auto stage = [&](int t, int bb) {
        const int l0 = chunk0 + t * TILE;
        const int rows = min(TILE, chunk0 + nrows - l0);
        #pragma unroll
        for (int i = 0; i < 2; i++) {
            const int r = sr + i * 16;
            if (r < rows) {
                const int gl = l0 + r;
                const size_t off = (size_t)gl * 64 + sc * 4;
                const float* ksrc = (gl < PAST) ? (cache_k + cbase + off)
                                                : (out_k + obase + off);
                const float* vsrc = (gl < PAST) ? (cache_v + cbase + off)
                                                : (out_v + obase + off);
                CP_ASYNC16(smem_u32(&kt[bb][r][sc * 4]), ksrc);
                CP_ASYNC16(smem_u32(&vt[bb][r][sc * 4]), vsrc);
            }
        }
    };

    stage(0, 0);
    CP_COMMIT();

    for (int t = 0; t < ntiles; t++) {
        const int bb   = t & 1;
        const int l0   = chunk0 + t * TILE;
        const int rows = min(TILE, chunk0 + nrows - l0);   // 32 or 16

        __syncthreads();   // buffer (t+1)&1 fully consumed (iter t-1)

        if (t + 1 < ntiles) {
            stage(t + 1, (t + 1) & 1);
            CP_COMMIT();
            CP_WAIT1();    // group t complete; group t+1 in flight
        } else {
            CP_WAIT0();
        }
        __syncthreads();   // staged tile visible to all

        // ---- copy-out cache rows to output KV (smem -> gmem) ----
        #pragma unroll
        for (int i = 0; i < 2; i++) {
            const int r = sr + i * 16;
            const int gl = l0 + r;
            if (r < rows && gl < PAST) {
                const size_t off = (size_t)gl * 64 + sc * 4;
                *(float4*)&out_k[obase + off] = *(const float4*)&kt[bb][r][sc * 4];
                *(float4*)&out_v[obase + off] = *(const float4*)&vt[bb][r][sc * 4];
            }
        }

        // ---- scores: thread = (queries qg*2, qg*2+1; k row kp) ----
        {
            float a0 = 0.f, a1 = 0.f;
            #pragma unroll
            for (int c = 0; c < 16; c++) {
                float4 k4 = *(const float4*)&kt[bb][kp][c * 4];
                float4 q0 = *(const float4*)&qs[qg * 2 + 0][c * 4];
                float4 q1 = *(const float4*)&qs[qg * 2 + 1][c * 4];
                a0 += k4.x*q0.x + k4.y*q0.y + k4.z*q0.z + k4.w*q0.w;
                a1 += k4.x*q1.x + k4.y*q1.y + k4.z*q1.z + k4.w*q1.w;
            }
            const bool valid = kp < rows;
            ptT[qg * 2 + 0][kp] = valid ? a0 : -1e30f;
            ptT[qg * 2 + 1][kp] = valid ? a1 : -1e30f;
        }
        __syncthreads();

        // ---- softmax partial: thread = (q=pq, seg=dc) over 2 scores ----
        {
            float2 p = *(const float2*)&ptT[pq][dc * 2];
            float mt = fmaxf(p.x, p.y);
            #pragma unroll
            for (int s = 8; s >= 1; s >>= 1)
                mt = fmaxf(mt, __shfl_xor_sync(0xffffffffu, mt, s, 16));
            const float mo = m_run[pq];
            const float mn = fmaxf(mo, mt);
            const float fc = __expf(mo - mn);
            p.x = __expf(p.x - mn);
            p.y = __expf(p.y - mn);
            *(float2*)&ptT[pq][dc * 2] = p;
            float ss = p.x + p.y;
            #pragma unroll
            for (int s = 8; s >= 1; s >>= 1)
                ss += __shfl_xor_sync(0xffffffffu, ss, s, 16);
            if (dc == 0) {
                m_run[pq] = mn;
                fac_s[pq] = fc;
                l_run[pq] = l_run[pq] * fc + ss;
            }
        }
        __syncthreads();

        // ---- AV: thread = (pq, dc): 4 dims over 32 rows ----
        {
            const float f = fac_s[pq];
            oacc.x *= f; oacc.y *= f; oacc.z *= f; oacc.w *= f;
            #pragma unroll
            for (int r0 = 0; r0 < TILE; r0 += 4) {
                float4 p4 = *(const float4*)&ptT[pq][r0];
                float4 v0 = *(const float4*)&vt[bb][r0 + 0][dc * 4];
                float4 v1 = *(const float4*)&vt[bb][r0 + 1][dc * 4];
                float4 v2 = *(const float4*)&vt[bb][r0 + 2][dc * 4];
                float4 v3 = *(const float4*)&vt[bb][r0 + 3][dc * 4];
                oacc.x += p4.x*v0.x + p4.y*v1.x + p4.z*v2.x + p4.w*v3.x;
                oacc.y += p4.x*v0.y + p4.y*v1.y + p4.z*v2.y + p4.w*v3.y;
                oacc.z += p4.x*v0.z + p4.y*v1.z + p4.z*v2.z + p4.w*v3.z;
                oacc.w += p4.x*v0.w + p4.y*v1.w + p4.z*v2.w + p4.w*v3.w;
            }
        }
    }

    // ---- write partials ----
    *(float4*)&g_po[(size_t)blockIdx.x * 1024 + pq * 64 + dc * 4] = oacc;
    if (tid < 16) {
        g_pm[blockIdx.x * 16 + tid] = m_run[tid];
        g_pl[blockIdx.x * 16 + tid] = l_run[tid];
    }
}

// ---------------------------------------------------------------------------
// Combine split partials -> g_obuf [B,S,H*hd]
// ---------------------------------------------------------------------------
__global__ __launch_bounds__(256)
void attn_reduce_kernel() {
    const int bh = blockIdx.x;
    const int tid = threadIdx.x;
    const int pq = tid >> 4, dc = tid & 15;
    const int base = bh * NSPLIT;

    float mm = -1e30f;
    #pragma unroll
    for (int s = 0; s < NSPLIT; s++)
        mm = fmaxf(mm, g_pm[(base + s) * 16 + pq]);

    float4 acc = make_float4(0.f, 0.f, 0.f, 0.f);
    float l = 0.f;
    #pragma unroll
    for (int s = 0; s < NSPLIT; s++) {
        float w = __expf(g_pm[(base + s) * 16 + pq] - mm);
        float4 o = *(const float4*)&g_po[(size_t)(base + s) * 1024 + pq * 64 + dc * 4];
        acc.x += w * o.x; acc.y += w * o.y;
        acc.z += w * o.z; acc.w += w * o.w;
        l += w * g_pl[(base + s) * 16 + pq];
    }
    float inv = 1.0f / l;
    const int b = bh >> 4, h = bh & 15;
    float4 r = make_float4(acc.x * inv, acc.y * inv, acc.z * inv, acc.w * inv);
    *(float4*)&g_obuf[(size_t)(b * 16 + pq) * D_MODEL + h * 64 + dc * 4] = r;
}

// ---------------------------------------------------------------------------
extern "C" void kernel_launch(void* const* d_in, const int* in_sizes, int n_in,
                              void* d_out, int out_size) {
    const float* x       = (const float*)d_in[0];
    const float* cache_k = (const float*)d_in[1];
    const float* cache_v = (const float*)d_in[2];
    const float* qkv_w   = (const float*)d_in[3];
    const float* qkv_b   = (const float*)d_in[4];
    const float* out_w   = (const float*)d_in[5];
    const float* out_b   = (const float*)d_in[6];

    float* out   = (float*)d_out;
    float* out_y = out + OUT_Y_OFF;
    float* out_k = out + OUT_K_OFF;
    float* out_v = out + OUT_V_OFF;

    float *qkv_p = nullptr, *obuf_p = nullptr;
    cudaGetSymbolAddress((void**)&qkv_p,  g_qkv);
    cudaGetSymbolAddress((void**)&obuf_p, g_obuf);

    // 1) QKV projection -> g_qkv [256,3072]
    gemm_bias_kernel<<<dim3(3072 / 64, M_ROWS / 64), 256>>>(
        x, qkv_w, qkv_b, qkv_p, 3072, D_MODEL);

    // 2) Append new K/V rows into out_k/out_v tails
    scatter_newkv_kernel<<<256, 256>>>(out_k, out_v);

    // 3) Fused attention + cache copy-out (split-KV x4, cp.async pipelined)
    attn_split_kernel<<<B_SZ * H_SZ * NSPLIT, 256>>>(cache_k, cache_v, out_k, out_v);

    // 4) Combine splits -> g_obuf
    attn_reduce_kernel<<<B_SZ * H_SZ, 256>>>();

    // 5) Output projection -> y
    gemm_bias_kernel<<<dim3(D_MODEL / 64, M_ROWS / 64), 256>>>(
        obuf_p, out_w, out_b, out_y, D_MODEL, D_MODEL);
}

// round 7
// speedup vs baseline: 1.5704x; 1.2244x over previous
#include <cuda_runtime.h>
#include <cuda_bf16.h>
#include <cstddef>

// Problem constants
#define B_SZ    16
#define S_SZ    16
#define H_SZ    16
#define HD      64
#define D_MODEL 1024
#define PAST    4096
#define L_TOT   4112
#define M_ROWS  256
#define NSPLIT  4

// Output layout offsets (floats): y | k | v
#define OUT_Y_OFF 0
#define OUT_K_OFF (256*1024)
#define OUT_V_OFF (OUT_K_OFF + 256*4112*64)

// Scratch (device globals; no allocations allowed)
__device__ float g_qkv [M_ROWS * 3 * D_MODEL];     // [256, 3072]
__device__ float g_obuf[M_ROWS * D_MODEL];         // [256, 1024]
__device__ float g_po  [256 * NSPLIT * 16 * 64];
__device__ float g_pm  [256 * NSPLIT * 16];
__device__ float g_pl  [256 * NSPLIT * 16];

// ---- tf32 helpers --------------------------------------------------------
__device__ __forceinline__ unsigned f2tf(float x) {
    unsigned r; asm("cvt.rna.tf32.f32 %0, %1;" : "=r"(r) : "f"(x)); return r;
}
// split x into hi (tf32 bits) + lo (tf32 bits of residual)
__device__ __forceinline__ void tf_split(float x, unsigned& hi, unsigned& lo) {
    hi = f2tf(x);
    lo = f2tf(x - __uint_as_float(hi));
}
__device__ __forceinline__ void mma_tf32(float& c0, float& c1, float& c2, float& c3,
                                         unsigned a0, unsigned a1, unsigned a2, unsigned a3,
                                         unsigned b0, unsigned b1) {
    asm volatile(
        "mma.sync.aligned.m16n8k8.row.col.f32.tf32.tf32.f32 "
        "{%0,%1,%2,%3}, {%4,%5,%6,%7}, {%8,%9}, {%0,%1,%2,%3};\n"
        : "+f"(c0), "+f"(c1), "+f"(c2), "+f"(c3)
        : "r"(a0), "r"(a1), "r"(a2), "r"(a3), "r"(b0), "r"(b1));
}

// ---------------------------------------------------------------------------
// GEMM: C[M,N] = A[M,K] @ W[N,K]^T + bias[N]   (row-major fp32)
// ---------------------------------------------------------------------------
__global__ __launch_bounds__(256)
void gemm_bias_kernel(const float* __restrict__ A, const float* __restrict__ W,
                      const float* __restrict__ bias, float* __restrict__ C,
                      int N, int K) {
    __shared__ float As[16][68];
    __shared__ float Bs[16][68];

    const int tid = threadIdx.x;
    const int tx = tid & 15;
    const int ty = tid >> 4;
    const int m0 = blockIdx.y * 64;
    const int n0 = blockIdx.x * 64;
    const int lr = tid >> 2;
    const int lk = (tid & 3) * 4;

    float c[4][4] = {};

    for (int k0 = 0; k0 < K; k0 += 16) {
        float4 a4 = *(const float4*)&A[(size_t)(m0 + lr) * K + k0 + lk];
        float4 b4 = *(const float4*)&W[(size_t)(n0 + lr) * K + k0 + lk];
        As[lk + 0][lr] = a4.x; As[lk + 1][lr] = a4.y;
        As[lk + 2][lr] = a4.z; As[lk + 3][lr] = a4.w;
        Bs[lk + 0][lr] = b4.x; Bs[lk + 1][lr] = b4.y;
        Bs[lk + 2][lr] = b4.z; Bs[lk + 3][lr] = b4.w;
        __syncthreads();

        #pragma unroll
        for (int kk = 0; kk < 16; kk++) {
            float4 av = *(const float4*)&As[kk][ty * 4];
            float4 bv = *(const float4*)&Bs[kk][tx * 4];
            c[0][0] += av.x * bv.x; c[0][1] += av.x * bv.y;
            c[0][2] += av.x * bv.z; c[0][3] += av.x * bv.w;
            c[1][0] += av.y * bv.x; c[1][1] += av.y * bv.y;
            c[1][2] += av.y * bv.z; c[1][3] += av.y * bv.w;
            c[2][0] += av.z * bv.x; c[2][1] += av.z * bv.y;
            c[2][2] += av.z * bv.z; c[2][3] += av.z * bv.w;
            c[3][0] += av.w * bv.x; c[3][1] += av.w * bv.y;
            c[3][2] += av.w * bv.z; c[3][3] += av.w * bv.w;
        }
        __syncthreads();
    }

    float4 bb = *(const float4*)&bias[n0 + tx * 4];
    #pragma unroll
    for (int i = 0; i < 4; i++) {
        float4 r = make_float4(c[i][0] + bb.x, c[i][1] + bb.y,
                               c[i][2] + bb.z, c[i][3] + bb.w);
        *(float4*)&C[(size_t)(m0 + ty * 4 + i) * N + n0 + tx * 4] = r;
    }
}

// ---------------------------------------------------------------------------
// Scatter freshly projected K/V rows into positions [4096, 4112).
// ---------------------------------------------------------------------------
__global__ __launch_bounds__(256)
void scatter_newkv_kernel(float* __restrict__ Kd, float* __restrict__ Vd) {
    const unsigned i = blockIdx.x * 256u + threadIdx.x;    // < 65536
    const unsigned c = i & 15u;
    const unsigned s = (i >> 4) & 15u;
    const unsigned h = (i >> 8) & 15u;
    const unsigned b = i >> 12;
    const size_t qoff = (size_t)(b * 16 + s) * 3072 + h * 64 + c * 4;
    const size_t doff = ((size_t)(b * 16 + h) * L_TOT + PAST + s) * 64 + c * 4;
    *(float4*)&Kd[doff] = *(const float4*)&g_qkv[qoff + 1024];
    *(float4*)&Vd[doff] = *(const float4*)&g_qkv[qoff + 2048];
}

// ---------------------------------------------------------------------------
// Fused attention + cache copy-out, split-KV x4.
// Score and AV GEMMs on tensor cores: mma.sync m16n8k8 tf32 with 3-pass
// hi/lo decomposition (error ~2^-21, fp32-class). 256 threads, 64-row tiles.
// Warp w owns: scores for KV rows w*8..w*8+7 (all 16 q); AV for output dims
// w*8..w*8+7 (all 16 q). O fragments live in registers across tiles.
// ---------------------------------------------------------------------------
__global__ __launch_bounds__(256)
void attn_split_kernel(const float* __restrict__ cache_k,
                       const float* __restrict__ cache_v,
                       float* __restrict__ out_k,
                       float* __restrict__ out_v) {
    __shared__ unsigned qh[16][68];    // q hi (tf32 bits)
    __shared__ unsigned ql[16][68];    // q lo
    __shared__ float kt[64][68];
    __shared__ float vt[64][68];
    __shared__ float ptT[16][68];
    __shared__ float m_run[16], l_run[16], fac_s[16];

    const int tid   = threadIdx.x;
    const int bh    = blockIdx.x >> 2;
    const int split = blockIdx.x & 3;
    const int b = bh >> 4, h = bh & 15;

    const int w  = tid >> 5;          // warp 0..7
    const int L  = tid & 31;          // lane
    const int lr4 = L >> 2;           // 0..7
    const int lc4 = L & 3;            // 0..3

    // ---- load q, scale by 1/8, split hi/lo into smem ----
    {
        const int q = tid >> 4, c4 = tid & 15;
        float4 qv = *(const float4*)&g_qkv[(size_t)(b * 16 + q) * 3072 + h * 64 + c4 * 4];
        qv.x *= 0.125f; qv.y *= 0.125f; qv.z *= 0.125f; qv.w *= 0.125f;
        unsigned hi, lo;
        tf_split(qv.x, hi, lo); qh[q][c4 * 4 + 0] = hi; ql[q][c4 * 4 + 0] = lo;
        tf_split(qv.y, hi, lo); qh[q][c4 * 4 + 1] = hi; ql[q][c4 * 4 + 1] = lo;
        tf_split(qv.z, hi, lo); qh[q][c4 * 4 + 2] = hi; ql[q][c4 * 4 + 2] = lo;
        tf_split(qv.w, hi, lo); qh[q][c4 * 4 + 3] = hi; ql[q][c4 * 4 + 3] = lo;
    }
    if (tid < 16) { m_run[tid] = -1e30f; l_run[tid] = 0.0f; }

    const int chunk0 = split * 1024;
    const int nrows  = (split == 3) ? 1040 : 1024;
    const int ntiles = (split == 3) ? 17 : 16;
    const size_t cbase = (size_t)bh * (PAST * 64);
    const size_t obase = (size_t)bh * (L_TOT * 64);

    // softmax mapping
    const int pq = tid >> 4;           // query 0..15
    const int dc = tid & 15;           // 4-score segment

    // O fragment (dims w*8 + lc4*2, +1 ; rows lr4, lr4+8)
    float oc0 = 0.f, oc1 = 0.f, oc2 = 0.f, oc3 = 0.f;

    for (int t = 0; t < ntiles; t++) {
        const int l0   = chunk0 + t * 64;
        const int rows = min(64, chunk0 + nrows - l0);   // 64 or 16
        __syncthreads();   // previous tile fully consumed

        // ---- stage K/V tile (fused copy-out for cache rows) ----
        #pragma unroll
        for (int i = 0; i < 4; i++) {
            int idx = i * 256 + tid;
            int r = idx >> 4, c = idx & 15;
            if (r < rows) {
                int gl = l0 + r;
                float4 k4, v4;
                if (gl < PAST) {
                    k4 = *(const float4*)&cache_k[cbase + (size_t)gl * 64 + c * 4];
                    v4 = *(const float4*)&cache_v[cbase + (size_t)gl * 64 + c * 4];
                    *(float4*)&out_k[obase + (size_t)gl * 64 + c * 4] = k4;
                    *(float4*)&out_v[obase + (size_t)gl * 64 + c * 4] = v4;
                } else {
                    k4 = *(const float4*)&out_k[obase + (size_t)gl * 64 + c * 4];
                    v4 = *(const float4*)&out_v[obase + (size_t)gl * 64 + c * 4];
                }
                *(float4*)&kt[r][c * 4] = k4;
                *(float4*)&vt[r][c * 4] = v4;
            }
        }
        __syncthreads();

        // ---- scores via 3xTF32 mma: warp w -> KV rows w*8..w*8+7 ----
        {
            float c0 = 0.f, c1 = 0.f, c2 = 0.f, c3 = 0.f;
            #pragma unroll
            for (int ks = 0; ks < 8; ks++) {
                const int k0 = ks * 8;
                // A = Q (row-major m16 x k8)
                unsigned ah0 = qh[lr4    ][k0 + lc4];
                unsigned ah1 = qh[lr4 + 8][k0 + lc4];
                unsigned ah2 = qh[lr4    ][k0 + 4 + lc4];
                unsigned ah3 = qh[lr4 + 8][k0 + 4 + lc4];
                unsigned al0 = ql[lr4    ][k0 + lc4];
                unsigned al1 = ql[lr4 + 8][k0 + lc4];
                unsigned al2 = ql[lr4    ][k0 + 4 + lc4];
                unsigned al3 = ql[lr4 + 8][k0 + 4 + lc4];
                // B = K^T (col-major k8 x n8): element (k, n) = kt[w*8+n][k]
                float b0f = kt[w * 8 + lr4][k0 + lc4];
                float b1f = kt[w * 8 + lr4][k0 + 4 + lc4];
                unsigned bh0, bl0, bh1, bl1;
                tf_split(b0f, bh0, bl0);
                tf_split(b1f, bh1, bl1);
                mma_tf32(c0, c1, c2, c3, ah0, ah1, ah2, ah3, bh0, bh1);
                mma_tf32(c0, c1, c2, c3, ah0, ah1, ah2, ah3, bl0, bl1);
                mma_tf32(c0, c1, c2, c3, al0, al1, al2, al3, bh0, bh1);
            }
            // C layout: c0 (m=lr4, n=lc4*2), c1 n+1, c2/c3 m+8
            const int n = w * 8 + lc4 * 2;
            ptT[lr4    ][n    ] = (n     < rows) ? c0 : -1e30f;
            ptT[lr4    ][n + 1] = (n + 1 < rows) ? c1 : -1e30f;
            ptT[lr4 + 8][n    ] = (n     < rows) ? c2 : -1e30f;
            ptT[lr4 + 8][n + 1] = (n + 1 < rows) ? c3 : -1e30f;
        }
        __syncthreads();

        // ---- softmax partial: thread = (q=pq, seg=dc) over 4 scores ----
        {
            float4 p = *(const float4*)&ptT[pq][dc * 4];
            float mt = fmaxf(fmaxf(p.x, p.y), fmaxf(p.z, p.w));
            #pragma unroll
            for (int s = 8; s >= 1; s >>= 1)
                mt = fmaxf(mt, __shfl_xor_sync(0xffffffffu, mt, s, 16));
            const float mo = m_run[pq];
            const float mn = fmaxf(mo, mt);
            const float fc = __expf(mo - mn);
            p.x = __expf(p.x - mn); p.y = __expf(p.y - mn);
            p.z = __expf(p.z - mn); p.w = __expf(p.w - mn);
            *(float4*)&ptT[pq][dc * 4] = p;
            float ss = p.x + p.y + p.z + p.w;
            #pragma unroll
            for (int s = 8; s >= 1; s >>= 1)
                ss += __shfl_xor_sync(0xffffffffu, ss, s, 16);
            if (dc == 0) {
                m_run[pq] = mn;
                fac_s[pq] = fc;
                l_run[pq] = l_run[pq] * fc + ss;
            }
        }
        __syncthreads();

        // ---- AV via 3xTF32 mma: warp w -> output dims w*8..w*8+7 ----
        {
            const float f0 = fac_s[lr4];
            const float f1 = fac_s[lr4 + 8];
            oc0 *= f0; oc1 *= f0; oc2 *= f1; oc3 *= f1;

            #pragma unroll
            for (int ks = 0; ks < 8; ks++) {
                const int k0 = ks * 8;        // kv-row block
                // A = P (row-major m16 x k8): ptT[q][kvrow]
                float af0 = ptT[lr4    ][k0 + lc4];
                float af1 = ptT[lr4 + 8][k0 + lc4];
                float af2 = ptT[lr4    ][k0 + 4 + lc4];
                float af3 = ptT[lr4 + 8][k0 + 4 + lc4];
                unsigned ah0, al0, ah1, al1, ah2, al2, ah3, al3;
                tf_split(af0, ah0, al0);
                tf_split(af1, ah1, al1);
                tf_split(af2, ah2, al2);
                tf_split(af3, ah3, al3);
                // B = V (col-major k8 x n8): element (k, n) = vt[k0+k][w*8+n]
                float b0f = vt[k0 + lc4    ][w * 8 + lr4];
                float b1f = vt[k0 + 4 + lc4][w * 8 + lr4];
                unsigned bh0, bl0, bh1, bl1;
                tf_split(b0f, bh0, bl0);
                tf_split(b1f, bh1, bl1);
                mma_tf32(oc0, oc1, oc2, oc3, ah0, ah1, ah2, ah3, bh0, bh1);
                mma_tf32(oc0, oc1, oc2, oc3, ah0, ah1, ah2, ah3, bl0, bl1);
                mma_tf32(oc0, oc1, oc2, oc3, al0, al1, al2, al3, bh0, bh1);
            }
        }
    }

    // ---- write partials: O frag (m=lr4/(lr4+8), d = w*8 + lc4*2, +1) ----
    {
        const size_t pbase = (size_t)blockIdx.x * 1024;
        const int d = w * 8 + lc4 * 2;
        *(float2*)&g_po[pbase + lr4       * 64 + d] = make_float2(oc0, oc1);
        *(float2*)&g_po[pbase + (lr4 + 8) * 64 + d] = make_float2(oc2, oc3);
    }
    if (tid < 16) {
        g_pm[blockIdx.x * 16 + tid] = m_run[tid];
        g_pl[blockIdx.x * 16 + tid] = l_run[tid];
    }
}

// ---------------------------------------------------------------------------
// Combine split partials -> g_obuf [B,S,H*hd]
// ---------------------------------------------------------------------------
__global__ __launch_bounds__(256)
void attn_reduce_kernel() {
    const int bh = blockIdx.x;
    const int tid = threadIdx.x;
    const int pq = tid >> 4, dc = tid & 15;
    const int base = bh * NSPLIT;

    float mm = -1e30f;
    #pragma unroll
    for (int s = 0; s < NSPLIT; s++)
        mm = fmaxf(mm, g_pm[(base + s) * 16 + pq]);

    float4 acc = make_float4(0.f, 0.f, 0.f, 0.f);
    float l = 0.f;
    #pragma unroll
    for (int s = 0; s < NSPLIT; s++) {
        float w = __expf(g_pm[(base + s) * 16 + pq] - mm);
        float4 o = *(const float4*)&g_po[(size_t)(base + s) * 1024 + pq * 64 + dc * 4];
        acc.x += w * o.x; acc.y += w * o.y;
        acc.z += w * o.z; acc.w += w * o.w;
        l += w * g_pl[(base + s) * 16 + pq];
    }
    float inv = 1.0f / l;
    const int b = bh >> 4, h = bh & 15;
    float4 r = make_float4(acc.x * inv, acc.y * inv, acc.z * inv, acc.w * inv);
    *(float4*)&g_obuf[(size_t)(b * 16 + pq) * D_MODEL + h * 64 + dc * 4] = r;
}

// ---------------------------------------------------------------------------
extern "C" void kernel_launch(void* const* d_in, const int* in_sizes, int n_in,
                              void* d_out, int out_size) {
    const float* x       = (const float*)d_in[0];
    const float* cache_k = (const float*)d_in[1];
    const float* cache_v = (const float*)d_in[2];
    const float* qkv_w   = (const float*)d_in[3];
    const float* qkv_b   = (const float*)d_in[4];
    const float* out_w   = (const float*)d_in[5];
    const float* out_b   = (const float*)d_in[6];

    float* out   = (float*)d_out;
    float* out_y = out + OUT_Y_OFF;
    float* out_k = out + OUT_K_OFF;
    float* out_v = out + OUT_V_OFF;

    float *qkv_p = nullptr, *obuf_p = nullptr;
    cudaGetSymbolAddress((void**)&qkv_p,  g_qkv);
    cudaGetSymbolAddress((void**)&obuf_p, g_obuf);

    // 1) QKV projection -> g_qkv [256,3072]
    gemm_bias_kernel<<<dim3(3072 / 64, M_ROWS / 64), 256>>>(
        x, qkv_w, qkv_b, qkv_p, 3072, D_MODEL);

    // 2) Append new K/V rows into out_k/out_v tails
    scatter_newkv_kernel<<<256, 256>>>(out_k, out_v);

    // 3) Fused attention + cache copy-out (split-KV x4, 3xTF32 tensor cores)
    attn_split_kernel<<<B_SZ * H_SZ * NSPLIT, 256>>>(cache_k, cache_v, out_k, out_v);

    // 4) Combine splits -> g_obuf
    attn_reduce_kernel<<<B_SZ * H_SZ, 256>>>();

    // 5) Output projection -> y
    gemm_bias_kernel<<<dim3(D_MODEL / 64, M_ROWS / 64), 256>>>(
        obuf_p, out_w, out_b, out_y, D_MODEL, D_MODEL);
}